// round 1
// baseline (speedup 1.0000x reference)
#include <cuda_runtime.h>
#include <cstdint>

// ---------------------------------------------------------------------------
// Problem constants
// B=8, N=128, S=100, F1=160
// Conv stack per image (1024 images):
//   L1: 1ch 100x100 -> conv3 98 -> pool 49  (10 ch)
//   L2: 10ch 49x49  -> conv3 47 -> pool 23
//   L3: 10ch 23x23  -> conv3 21 -> pool 10
//   L4: 10ch 10x10  -> conv3 8  -> pool 4   -> 10*4*4 = 160 features
// ---------------------------------------------------------------------------

#define NIMG 1024

// Scratch buffers (static device allocations; no cudaMalloc allowed)
__device__ float g_P1[NIMG * 10 * 49 * 49];
__device__ float g_P2[NIMG * 10 * 23 * 23];
__device__ float g_P3[NIMG * 10 * 10 * 10];
__device__ float g_Hf [NIMG * 160];
__device__ float g_dk1[NIMG * 256];
__device__ float g_dkf[NIMG * 512];
__device__ float g_xx [NIMG];
__device__ float g_K  [8 * 128 * 128];
__device__ float g_B1 [NIMG * 160];   // message-passing outputs
__device__ float g_avg[NIMG * 160];
__device__ float g_H2 [NIMG * 160];
__device__ float g_H4 [NIMG * 160];
__device__ float g_H6 [NIMG * 160];

// ---------------------------------------------------------------------------
// Fused conv3x3(VALID) + ReLU + maxpool2x2 kernel.
// One block per image. Whole input tile + weights live in shared memory.
// Each thread computes ONE pooled output pixel for ALL 10 output channels:
// 40 register accumulators (2x2 conv window x 10 oc). Weight loads are
// warp-broadcast; each weight load feeds 2 FMAs (two conv columns).
// ---------------------------------------------------------------------------
template<int IC, int IS>
__global__ void conv_pool_kernel(const float* __restrict__ in,
                                 const float* __restrict__ w,
                                 const float* __restrict__ bias,
                                 float* __restrict__ out)
{
    constexpr int CS = IS - 2;     // conv output size
    constexpr int OS = CS / 2;     // pooled output size
    constexpr int IN_ELEMS = IC * IS * IS;
    constexpr int W_ELEMS  = 10 * IC * 9;

    extern __shared__ float smem[];
    float* sIn = smem;                 // IC*IS*IS
    float* sW  = smem + IN_ELEMS;      // 10*IC*9
    float* sB  = sW + W_ELEMS;         // 10

    const int img = blockIdx.x;
    const float* gIn = in + (size_t)img * IN_ELEMS;

    for (int i = threadIdx.x; i < IN_ELEMS; i += blockDim.x) sIn[i] = gIn[i];
    for (int i = threadIdx.x; i < W_ELEMS;  i += blockDim.x) sW[i]  = w[i];
    if (threadIdx.x < 10) sB[threadIdx.x] = bias[threadIdx.x];
    __syncthreads();

    for (int item = threadIdx.x; item < OS * OS; item += blockDim.x) {
        const int oy = item / OS;
        const int ox = item % OS;
        const int iy0 = 2 * oy;
        const int ix0 = 2 * ox;

        float acc[40];  // [(dy*2+dx)*10 + oc]
        #pragma unroll
        for (int oc = 0; oc < 10; ++oc) {
            float bv = sB[oc];
            acc[oc] = bv; acc[10 + oc] = bv; acc[20 + oc] = bv; acc[30 + oc] = bv;
        }

        for (int ic = 0; ic < IC; ++ic) {
            const float* bIn = sIn + ic * IS * IS;
            const float* bW  = sW + ic * 9;  // + oc*IC*9
            #pragma unroll
            for (int r = 0; r < 4; ++r) {
                const float* rowp = bIn + (iy0 + r) * IS + ix0;
                float v[4];
                v[0] = rowp[0]; v[1] = rowp[1]; v[2] = rowp[2]; v[3] = rowp[3];
                #pragma unroll
                for (int dy = 0; dy < 2; ++dy) {
                    const int ky = r - dy;
                    if (ky >= 0 && ky <= 2) {
                        #pragma unroll
                        for (int kx = 0; kx < 3; ++kx) {
                            #pragma unroll
                            for (int oc = 0; oc < 10; ++oc) {
                                const float wv = bW[oc * IC * 9 + ky * 3 + kx];
                                acc[(dy * 2 + 0) * 10 + oc] += wv * v[kx];
                                acc[(dy * 2 + 1) * 10 + oc] += wv * v[kx + 1];
                            }
                        }
                    }
                }
            }
        }

        #pragma unroll
        for (int oc = 0; oc < 10; ++oc) {
            float m = fmaxf(fmaxf(acc[oc], acc[10 + oc]),
                            fmaxf(acc[20 + oc], acc[30 + oc]));
            m = fmaxf(m, 0.0f);  // relu-then-maxpool == max(...,0)
            out[((size_t)img * 10 + oc) * (OS * OS) + item] = m;
        }
    }
}

// ---------------------------------------------------------------------------
// Tiled SGEMM-NT:  C[M,N] = act( A[M,K] @ B[N,K]^T + bias[N] )
// (A row-major, B row-major with K contiguous -> "NT").
// Optional batching via element strides (blockIdx.z).
// ---------------------------------------------------------------------------
template<int BM, int BN, int TM, int TN, bool TANH, bool HASBIAS>
__global__ void gemm_nt_kernel(const float* __restrict__ A,
                               const float* __restrict__ B,
                               const float* __restrict__ bias,
                               float* __restrict__ C,
                               int M, int N, int K,
                               long long sA, long long sB, long long sC)
{
    constexpr int TX = BN / TN;              // threads in x
    __shared__ float As[16 * (BM + 1)];
    __shared__ float Bs[16 * (BN + 1)];

    const int tid = threadIdx.x;
    const int bz  = blockIdx.z;
    const float* Ab = A + bz * sA;
    const float* Bb = B + bz * sB;
    float* Cb = C + bz * sC;

    const int row0 = blockIdx.y * BM;
    const int col0 = blockIdx.x * BN;
    const int ty = tid / TX;
    const int tx = tid % TX;

    float acc[TM][TN] = {};

    for (int k0 = 0; k0 < K; k0 += 16) {
        for (int li = tid; li < BM * 16; li += blockDim.x) {
            const int r = li >> 4, kk = li & 15;
            const int gr = row0 + r;
            As[kk * (BM + 1) + r] = (gr < M) ? Ab[(size_t)gr * K + k0 + kk] : 0.0f;
        }
        for (int li = tid; li < BN * 16; li += blockDim.x) {
            const int r = li >> 4, kk = li & 15;
            const int gc = col0 + r;
            Bs[kk * (BN + 1) + r] = (gc < N) ? Bb[(size_t)gc * K + k0 + kk] : 0.0f;
        }
        __syncthreads();

        #pragma unroll
        for (int kk = 0; kk < 16; ++kk) {
            float a[TM], b[TN];
            #pragma unroll
            for (int i = 0; i < TM; ++i) a[i] = As[kk * (BM + 1) + ty * TM + i];
            #pragma unroll
            for (int j = 0; j < TN; ++j) b[j] = Bs[kk * (BN + 1) + tx * TN + j];
            #pragma unroll
            for (int i = 0; i < TM; ++i)
                #pragma unroll
                for (int j = 0; j < TN; ++j)
                    acc[i][j] += a[i] * b[j];
        }
        __syncthreads();
    }

    #pragma unroll
    for (int i = 0; i < TM; ++i) {
        const int gr = row0 + ty * TM + i;
        if (gr >= M) continue;
        #pragma unroll
        for (int j = 0; j < TN; ++j) {
            const int gc = col0 + tx * TN + j;
            if (gc >= N) continue;
            float v = acc[i][j];
            if (HASBIAS) v += bias[gc];
            if (TANH) v = tanhf(v);
            Cb[(size_t)gr * N + gc] = v;
        }
    }
}

// ---------------------------------------------------------------------------
// xx[r] = sum_k dkf[r,k]^2   (K = 512)
// ---------------------------------------------------------------------------
__global__ void rowsq_kernel(const float* __restrict__ x, float* __restrict__ xx)
{
    const int r = blockIdx.x;
    float s = 0.0f;
    for (int k = threadIdx.x; k < 512; k += 128) {
        float v = x[(size_t)r * 512 + k];
        s += v * v;
    }
    __shared__ float red[128];
    red[threadIdx.x] = s;
    __syncthreads();
    for (int st = 64; st > 0; st >>= 1) {
        if (threadIdx.x < st) red[threadIdx.x] += red[threadIdx.x + st];
        __syncthreads();
    }
    if (threadIdx.x == 0) xx[r] = red[0];
}

// ---------------------------------------------------------------------------
// Softmax kernel (in place on xy -> K). Per-row constants (-xx[n], row mean)
// are softmax-invariant and dropped:  K[n,m] = softmax_m((2*xy - xx[m])/sigma)
// ---------------------------------------------------------------------------
__global__ void softmax_kernel(float* __restrict__ xy,
                               const float* __restrict__ xx,
                               const float* __restrict__ sigma)
{
    const int row = blockIdx.x;          // row = b*128 + n
    const int b = row >> 7;
    const int t = threadIdx.x;           // 128 threads
    const float inv_s = 1.0f / sigma[0];
    float* L = xy + (size_t)row * 128;

    float v = (2.0f * L[t] - xx[b * 128 + t]) * inv_s;

    __shared__ float red[128];
    red[t] = v;
    __syncthreads();
    for (int st = 64; st > 0; st >>= 1) {
        if (t < st) red[t] = fmaxf(red[t], red[t + st]);
        __syncthreads();
    }
    const float mx = red[0];
    __syncthreads();
    const float e = expf(v - mx);
    red[t] = e;
    __syncthreads();
    for (int st = 64; st > 0; st >>= 1) {
        if (t < st) red[t] += red[t + st];
        __syncthreads();
    }
    L[t] = e / red[0];
}

// ---------------------------------------------------------------------------
// out[b,n,:] = sum_m K[b,n,m] * z[b,m,:]   (d = 160, m = 128)
// grid (128, 8), block 160; z loads coalesced across threads.
// ---------------------------------------------------------------------------
__global__ void mix_kernel(const float* __restrict__ Kw,
                           const float* __restrict__ z,
                           float* __restrict__ out)
{
    const int b = blockIdx.y, n = blockIdx.x, t = threadIdx.x;
    __shared__ float w[128];
    const float* Kr = Kw + ((size_t)b * 128 + n) * 128;
    if (t < 128) w[t] = Kr[t];
    __syncthreads();
    const float* zb = z + (size_t)b * 128 * 160;
    float acc = 0.0f;
    #pragma unroll 8
    for (int m = 0; m < 128; ++m)
        acc += w[m] * zb[(size_t)m * 160 + t];
    out[((size_t)b * 128 + n) * 160 + t] = acc;
}

// out[i] = (a[i] + b[i]) * 0.5
__global__ void avg_kernel(const float* __restrict__ a,
                           const float* __restrict__ b,
                           float* __restrict__ o, int n)
{
    const int i = blockIdx.x * blockDim.x + threadIdx.x;
    if (i < n) o[i] = (a[i] + b[i]) * 0.5f;
}

// out[b] = exp( sum_d max_n(H6[b,n,d]) * Wc[d] + bc )
__global__ void final_kernel(const float* __restrict__ H6,
                             const float* __restrict__ Wc,
                             const float* __restrict__ bc,
                             float* __restrict__ out)
{
    const int b = blockIdx.x;
    const int t = threadIdx.x;   // 160 threads
    float m = -3.0e38f;
    for (int n = 0; n < 128; ++n)
        m = fmaxf(m, H6[((size_t)b * 128 + n) * 160 + t]);
    __shared__ float red[160];
    red[t] = m * Wc[t];
    __syncthreads();
    if (t == 0) {
        float s = 0.0f;
        for (int i = 0; i < 160; ++i) s += red[i];
        out[b] = expf(s + bc[0]);
    }
}

// ---------------------------------------------------------------------------
// Host launcher
// ---------------------------------------------------------------------------
extern "C" void kernel_launch(void* const* d_in, const int* in_sizes, int n_in,
                              void* d_out, int out_size)
{
    const float* H     = (const float*)d_in[0];
    const float* w1    = (const float*)d_in[1];
    const float* b1    = (const float*)d_in[2];
    const float* w2    = (const float*)d_in[3];
    const float* b2    = (const float*)d_in[4];
    const float* w3    = (const float*)d_in[5];
    const float* b3    = (const float*)d_in[6];
    const float* w4    = (const float*)d_in[7];
    const float* b4    = (const float*)d_in[8];
    const float* Wdk1  = (const float*)d_in[9];
    const float* bdk1  = (const float*)d_in[10];
    const float* Wdk2  = (const float*)d_in[11];
    const float* bdk2  = (const float*)d_in[12];
    const float* Wt1   = (const float*)d_in[13];
    const float* bt1   = (const float*)d_in[14];
    const float* Wt2   = (const float*)d_in[15];
    const float* bt2   = (const float*)d_in[16];
    const float* Wt3   = (const float*)d_in[17];
    const float* bt3   = (const float*)d_in[18];
    const float* sigma = (const float*)d_in[19];
    const float* Wc    = (const float*)d_in[20];
    const float* bc    = (const float*)d_in[21];

    float *p1, *p2, *p3, *hf, *dk1, *dkf, *xx, *Kp, *bmp, *avg, *h2, *h4, *h6;
    cudaGetSymbolAddress((void**)&p1,  g_P1);
    cudaGetSymbolAddress((void**)&p2,  g_P2);
    cudaGetSymbolAddress((void**)&p3,  g_P3);
    cudaGetSymbolAddress((void**)&hf,  g_Hf);
    cudaGetSymbolAddress((void**)&dk1, g_dk1);
    cudaGetSymbolAddress((void**)&dkf, g_dkf);
    cudaGetSymbolAddress((void**)&xx,  g_xx);
    cudaGetSymbolAddress((void**)&Kp,  g_K);
    cudaGetSymbolAddress((void**)&bmp, g_B1);
    cudaGetSymbolAddress((void**)&avg, g_avg);
    cudaGetSymbolAddress((void**)&h2,  g_H2);
    cudaGetSymbolAddress((void**)&h4,  g_H4);
    cudaGetSymbolAddress((void**)&h6,  g_H6);

    // Dynamic shared-memory sizes for the conv kernels
    const size_t smem1 = (1  * 100 * 100 + 10 * 1  * 9 + 10) * sizeof(float); // 40.4 KB
    const size_t smem2 = (10 * 49  * 49  + 10 * 10 * 9 + 10) * sizeof(float); // 99.7 KB
    const size_t smem3 = (10 * 23  * 23  + 10 * 10 * 9 + 10) * sizeof(float); // 24.8 KB
    const size_t smem4 = (10 * 10  * 10  + 10 * 10 * 9 + 10) * sizeof(float); //  7.6 KB
    cudaFuncSetAttribute(conv_pool_kernel<10, 49>,
                         cudaFuncAttributeMaxDynamicSharedMemorySize, (int)smem2);

    // ---- Conv stack ----
    conv_pool_kernel<1, 100><<<NIMG, 256, smem1>>>(H,  w1, b1, p1);
    conv_pool_kernel<10, 49><<<NIMG, 256, smem2>>>(p1, w2, b2, p2);
    conv_pool_kernel<10, 23><<<NIMG, 256, smem3>>>(p2, w3, b3, p3);
    conv_pool_kernel<10, 10><<<NIMG, 256, smem4>>>(p3, w4, b4, hf);

    // ---- Deep-kernel MLP: dkf = tanh(tanh(Hf@Wdk1^T+b)@Wdk2^T+b) ----
    gemm_nt_kernel<64, 64, 4, 4, true, true><<<dim3(4, 16, 1), 256>>>(
        hf, Wdk1, bdk1, dk1, 1024, 256, 160, 0, 0, 0);
    gemm_nt_kernel<64, 64, 4, 4, true, true><<<dim3(8, 16, 1), 256>>>(
        dk1, Wdk2, bdk2, dkf, 1024, 512, 256, 0, 0, 0);

    // ---- Attention matrix K (identical for all 3 message-passing rounds) ----
    rowsq_kernel<<<NIMG, 128>>>(dkf, xx);
    gemm_nt_kernel<32, 32, 2, 2, false, false><<<dim3(4, 4, 8), 256>>>(
        dkf, dkf, nullptr, Kp, 128, 128, 512,
        128LL * 512, 128LL * 512, 128LL * 128);
    softmax_kernel<<<NIMG, 128>>>(Kp, xx, sigma);

    const int AVGN = NIMG * 160;
    dim3 mixg(128, 8);

    // ---- Round 1: H1 = K@Hf; H2 = tanh(((Hf+H1)/2)@Wt1^T + bt1) ----
    mix_kernel<<<mixg, 160>>>(Kp, hf, bmp);
    avg_kernel<<<(AVGN + 255) / 256, 256>>>(hf, bmp, avg, AVGN);
    gemm_nt_kernel<64, 64, 4, 4, true, true><<<dim3(3, 16, 1), 256>>>(
        avg, Wt1, bt1, h2, 1024, 160, 160, 0, 0, 0);

    // ---- Round 2 ----
    mix_kernel<<<mixg, 160>>>(Kp, h2, bmp);
    avg_kernel<<<(AVGN + 255) / 256, 256>>>(bmp, h2, avg, AVGN);
    gemm_nt_kernel<64, 64, 4, 4, true, true><<<dim3(3, 16, 1), 256>>>(
        avg, Wt2, bt2, h4, 1024, 160, 160, 0, 0, 0);

    // ---- Round 3 ----
    mix_kernel<<<mixg, 160>>>(Kp, h4, bmp);
    avg_kernel<<<(AVGN + 255) / 256, 256>>>(bmp, h4, avg, AVGN);
    gemm_nt_kernel<64, 64, 4, 4, true, true><<<dim3(3, 16, 1), 256>>>(
        avg, Wt3, bt3, h6, 1024, 160, 160, 0, 0, 0);

    // ---- Max over N, final linear, exp ----
    final_kernel<<<8, 160>>>(h6, Wc, bc, (float*)d_out);
}